// round 16
// baseline (speedup 1.0000x reference)
#include <cuda_runtime.h>
#include <cuda_bf16.h>
#include <math.h>
#include <stdint.h>

#define NN 2048
#define DD 64
#define PP 32
#define NSTOP 512
#define KIN 4131          // 2*N + 3 + P
#define KPAD 4160         // 130 chunks of 32
#define NCHUNK 130
#define BM 128
#define BN 128
#define NSTG 4
#define TILE_U32 2048     // 128x32 bf16 = 2048 uint32 = 8KB
#define STAGE_U32 4096
#define STAGE_B 16384
#define GEMM_SMEM (NSTG * STAGE_B)

// ---------------- scratch (device globals: allocation-free) ----------------
__device__ unsigned d_kmask[NN / 32];
__device__ int   d_kpre[NN / 32];    // exclusive prefix of popc(kmask)
__device__ int   d_klist[NSTOP];
__device__ int   d_nk;
__device__ __align__(16) float d_xn[NN * DD];
__device__ __align__(16) float d_xnc[NSTOP * DD];
__device__ __align__(16) float d_embc[NSTOP * DD];
__device__ __align__(16) float d_aggn[NN * DD];
__device__ __align__(16) float d_aggs[2 * NSTOP * DD];   // per-half partial sums
__device__ int   d_degp[2 * NSTOP];                      // per-half partial degrees
__device__ float d_pref[NN * PP];
__device__ float d_av[NN];
__device__ float d_bv[NN];
// m16n8k16 bf16 fragment-packed operands
__device__ __align__(128) uint32_t d_apack[(size_t)NN * KPAD / 2];
__device__ __align__(128) uint32_t d_bpack[(size_t)NN * KPAD / 2];

// ---------------- helpers ----------------
__device__ __forceinline__ uint32_t smem_u32(const void* p) {
    uint32_t a;
    asm("{ .reg .u64 t; cvta.to.shared.u64 t, %1; cvt.u32.u64 %0, t; }" : "=r"(a) : "l"(p));
    return a;
}
__device__ __forceinline__ uint32_t pack_bf16(float a, float b) {
    __nv_bfloat162 h = __floats2bfloat162_rn(a, b);
    return *(uint32_t*)&h;
}
#define CP_ASYNC16(dst, src) \
    asm volatile("cp.async.cg.shared.global [%0], [%1], 16;" :: "r"(dst), "l"(src) : "memory")
#define CP_COMMIT() asm volatile("cp.async.commit_group;" ::: "memory")
#define CP_WAIT(n)  asm volatile("cp.async.wait_group %0;" :: "n"(n) : "memory")

#define MMA16(c, a, b) \
    asm volatile("mma.sync.aligned.m16n8k16.row.col.f32.bf16.bf16.f32 " \
        "{%0,%1,%2,%3},{%4,%5,%6,%7},{%8,%9},{%0,%1,%2,%3};" \
        : "+f"((c)[0]), "+f"((c)[1]), "+f"((c)[2]), "+f"((c)[3]) \
        : "r"((a)[0]), "r"((a)[1]), "r"((a)[2]), "r"((a)[3]), \
          "r"((b)[0]), "r"((b)[1]))

__device__ __forceinline__ int keep_bit(int i) {
    return (d_kmask[i >> 5] >> (i & 31)) & 1;
}

// ---------------- prep: zero mask, scatter stops, prefix table (1 block) ------
__global__ void k_prep(const int* __restrict__ stops) {      // 1 block, 512 thr
    __shared__ int cnt[NN / 32];
    int t = threadIdx.x;
    if (t < NN / 32) d_kmask[t] = 0u;
    __syncthreads();
    int s = stops[t];
    atomicOr(&d_kmask[s >> 5], 1u << (s & 31));
    __syncthreads();
    if (t < NN / 32) cnt[t] = __popc(d_kmask[t]);
    __syncthreads();
    if (t == 0) {
        int acc = 0;
        #pragma unroll
        for (int q = 0; q < NN / 32; q++) {
            d_kpre[q] = acc;
            acc += cnt[q];
        }
        d_nk = acc;
    }
}

// ---------------- fused: zero aggn + row-normalize + compaction ----------------
__global__ void k_initc(const float* __restrict__ emb) {     // grid NN, block 64
    int i = blockIdx.x;
    int t = threadIdx.x;
    int idx = i * DD + t;
    d_aggn[idx] = 0.f;

    float v = emb[idx];
    float s = v * v;
    #pragma unroll
    for (int o = 16; o; o >>= 1) s += __shfl_down_sync(0xffffffffu, s, o);
    __shared__ float ws[2];
    if ((t & 31) == 0) ws[t >> 5] = s;
    __syncthreads();
    float norm = fmaxf(sqrtf(ws[0] + ws[1]), 1e-8f);
    float xnv = v / norm;
    d_xn[idx] = xnv;

    unsigned w = d_kmask[i >> 5];
    if ((w >> (i & 31)) & 1) {
        int pos = d_kpre[i >> 5] + __popc(w & ((1u << (i & 31)) - 1u));
        if (t == 0) d_klist[pos] = i;
        d_xnc[pos * DD + t] = xnv;
        d_embc[pos * DD + t] = v;
    }
}

// ---------------- sim+agg partials: 2 rows/block, j-range split in halves ------
__global__ void k_aggv3p() {                                 // grid (NSTOP/2, 2), 256
    int b0 = blockIdx.x * 2, y = blockIdx.y, t = threadIdx.x;
    int nk = d_nk;
    if (b0 >= nk) return;
    bool have1 = (b0 + 1) < nk;
    __shared__ __align__(16) float xi[2 * DD];
    __shared__ unsigned mw[2][8];
    __shared__ float agg0[256];
    __shared__ float agg1[256];
    if (t < 2 * DD) xi[t] = d_xnc[b0 * DD + t];
    __syncthreads();

    int lane = t & 31, w = t >> 5;       // warp w owns j in [y*256+32w, +32)
    int qt = lane & 3;
    const float4* xq0 = (const float4*)(xi + qt * 16);
    const float4* xq1 = (const float4*)(xi + DD + qt * 16);
    float4 p0 = xq0[0], p1 = xq0[1], p2 = xq0[2], p3 = xq0[3];
    float4 q0 = xq1[0], q1 = xq1[1], q2 = xq1[2], q3 = xq1[3];

    unsigned w0 = 0, w1 = 0;
    #pragma unroll
    for (int sub = 0; sub < 4; sub++) {
        int j = y * 256 + w * 32 + sub * 8 + (lane >> 2);
        const float4* xj = (const float4*)(d_xnc + j * DD + qt * 16);
        float4 a0 = xj[0], a1 = xj[1], a2 = xj[2], a3 = xj[3];
        float s0 = a0.x * p0.x + a0.y * p0.y + a0.z * p0.z + a0.w * p0.w
                 + a1.x * p1.x + a1.y * p1.y + a1.z * p1.z + a1.w * p1.w
                 + a2.x * p2.x + a2.y * p2.y + a2.z * p2.z + a2.w * p2.w
                 + a3.x * p3.x + a3.y * p3.y + a3.z * p3.z + a3.w * p3.w;
        float s1 = a0.x * q0.x + a0.y * q0.y + a0.z * q0.z + a0.w * q0.w
                 + a1.x * q1.x + a1.y * q1.y + a1.z * q1.z + a1.w * q1.w
                 + a2.x * q2.x + a2.y * q2.y + a2.z * q2.z + a2.w * q2.w
                 + a3.x * q3.x + a3.y * q3.y + a3.z * q3.z + a3.w * q3.w;
        s0 += __shfl_xor_sync(0xffffffffu, s0, 1);
        s0 += __shfl_xor_sync(0xffffffffu, s0, 2);
        s1 += __shfl_xor_sync(0xffffffffu, s1, 1);
        s1 += __shfl_xor_sync(0xffffffffu, s1, 2);
        bool pr0 = (qt == 0) && (j < nk) && (j != b0) && (s0 > 0.5f);
        bool pr1 = (qt == 0) && have1 && (j < nk) && (j != b0 + 1) && (s1 > 0.5f);
        unsigned m0 = __ballot_sync(0xffffffffu, pr0);       // bits at 4r
        unsigned m1 = __ballot_sync(0xffffffffu, pr1);
        unsigned c0 = 0, c1 = 0;
        #pragma unroll
        for (int r = 0; r < 8; r++) {
            c0 |= ((m0 >> (4 * r)) & 1u) << r;
            c1 |= ((m1 >> (4 * r)) & 1u) << r;
        }
        w0 |= c0 << (sub * 8);
        w1 |= c1 << (sub * 8);
    }
    if (lane == 0) { mw[0][w] = w0; mw[1][w] = w1; }
    __syncthreads();

    int deg0 = 0, deg1 = 0;
    #pragma unroll
    for (int q = 0; q < 8; q++) { deg0 += __popc(mw[0][q]); deg1 += __popc(mw[1][q]); }
    if (t == 0) {
        d_degp[y * NSTOP + b0] = deg0;
        d_degp[y * NSTOP + b0 + 1] = deg1;
    }

    int d = t & 63, part = t >> 6;       // 4 parts x 2 words each
    float s0 = 0.f, s1 = 0.f;
    #pragma unroll
    for (int q = part * 2; q < part * 2 + 2; q++) {
        unsigned mm = mw[0][q];
        while (mm) {
            int bit = __ffs(mm) - 1;
            mm &= mm - 1;
            s0 += d_embc[(y * 256 + q * 32 + bit) * DD + d];
        }
        mm = mw[1][q];
        while (mm) {
            int bit = __ffs(mm) - 1;
            mm &= mm - 1;
            s1 += d_embc[(y * 256 + q * 32 + bit) * DD + d];
        }
    }
    agg0[t] = s0;
    agg1[t] = s1;
    __syncthreads();
    if (t < DD) {
        d_aggs[(size_t)(y * NSTOP + b0) * DD + t] =
            agg0[t] + agg0[t + 64] + agg0[t + 128] + agg0[t + 192];
    } else if (t < 2 * DD && have1) {
        int dd = t - DD;
        d_aggs[(size_t)(y * NSTOP + b0 + 1) * DD + dd] =
            agg1[dd] + agg1[dd + 64] + agg1[dd + 128] + agg1[dd + 192];
    }
}

// ---------------- combine halves + divide ----------------
__global__ void k_aggdiv() {                                 // grid NSTOP, block 64
    int b = blockIdx.x, t = threadIdx.x;
    if (b >= d_nk) return;
    int deg = d_degp[b] + d_degp[NSTOP + b];
    float s = d_aggs[(size_t)b * DD + t] + d_aggs[(size_t)(NSTOP + b) * DD + t];
    d_aggn[d_klist[b] * DD + t] = s / fmaxf((float)deg, 1.0f);
}

// ---------------- pref v2: smem-staged weights, 8 rows/block ----------------
__global__ __launch_bounds__(256) void k_pref2(const float* __restrict__ emb,
                       const float* __restrict__ llw, const float* __restrict__ llb,
                       const float* __restrict__ lrw, const float* __restrict__ ew) {
    __shared__ float wl[DD * PP];        // transposed: wl[d*32+p]
    __shared__ float wr[DD * PP];
    __shared__ float rows[8 * 2 * DD];   // per row: agg[64] then emb[64]
    int t = threadIdx.x;
    int i0 = blockIdx.x * 8;
    #pragma unroll
    for (int q = 0; q < 8; q++) {
        int idx = q * 256 + t;           // idx = p*64+d
        int p = idx >> 6, d = idx & 63;
        wl[d * PP + p] = llw[idx];
        wr[d * PP + p] = lrw[idx];
    }
    #pragma unroll
    for (int q = 0; q < 2; q++) {
        int idx = q * 256 + t;           // 512 floats each array
        int r = idx >> 6, d = idx & 63;
        rows[r * 128 + d] = d_aggn[(i0 + r) * DD + d];
        rows[r * 128 + 64 + d] = emb[(i0 + r) * DD + d];
    }
    __syncthreads();

    int r = t >> 5, p = t & 31;
    int i = i0 + r;
    const float* ar = rows + r * 128;
    const float* er = ar + DD;
    float s = llb[p];
    #pragma unroll
    for (int d = 0; d < DD; d++)
        s += ar[d] * wl[d * PP + p] + er[d] * wr[d * PP + p];
    d_pref[i * PP + p] = s;
    float a = s * ew[p];
    float b = s * ew[PP + p];
    #pragma unroll
    for (int o = 16; o; o >>= 1) {
        a += __shfl_down_sync(0xffffffffu, a, o);
        b += __shfl_down_sync(0xffffffffu, b, o);
    }
    if (p == 0) { d_av[i] = a; d_bv[i] = b; }
}

// ---------------- combined value at (i,k) ----------------
__device__ __forceinline__ float comb_val(int i, int k, const float* __restrict__ dist,
                                          float eb, float wkf, float vhf) {
    if (k < PP) return d_pref[i * PP + k];
    if (k < PP + NN) {
        float e = d_av[i] + d_bv[k - PP] + eb;
        return (e >= 0.f) ? e : 0.01f * e;
    }
    if (k < PP + 2 * NN) return dist[(size_t)i * NN + (k - PP - NN)];
    if (k == PP + 2 * NN) return wkf;
    if (k == PP + 2 * NN + 1) return vhf;
    if (k == PP + 2 * NN + 2) return keep_bit(i) ? 1.f : 0.f;
    return 0.f;
}

// ---------------- merged fill: y<16 -> A pack, y>=16 -> B pack ----------------
__global__ __launch_bounds__(512) void k_fill(const float* __restrict__ dist,
                                              const float* __restrict__ edge_b,
                                              const int* __restrict__ wk,
                                              const int* __restrict__ vh,
                                              const float* __restrict__ combw) {
    int kc = blockIdx.x;
    int y = blockIdx.y;
    int t = threadIdx.x;                 // 512
    int lane = t & 31;
    if (y < 16) {
        // ---- A pack: fragment-offset iteration, coalesced uint4 stores ----
        int mt = y;
        int fragq = t >> 5;              // 0..15
        int ki = fragq >> 3, mi = fragq & 7;
        int g = lane >> 2, tg = lane & 3;
        int i0 = mt * 128 + mi * 16 + g;
        int i1 = i0 + 8;
        int kA = kc * 32 + ki * 16 + tg * 2;
        int kB = kA + 8;
        float eb = edge_b[0], wkf = (float)wk[0], vhf = (float)vh[0];
        uint4 v;
        v.x = pack_bf16(comb_val(i0, kA, dist, eb, wkf, vhf), comb_val(i0, kA + 1, dist, eb, wkf, vhf));
        v.y = pack_bf16(comb_val(i1, kA, dist, eb, wkf, vhf), comb_val(i1, kA + 1, dist, eb, wkf, vhf));
        v.z = pack_bf16(comb_val(i0, kB, dist, eb, wkf, vhf), comb_val(i0, kB + 1, dist, eb, wkf, vhf));
        v.w = pack_bf16(comb_val(i1, kB, dist, eb, wkf, vhf), comb_val(i1, kB + 1, dist, eb, wkf, vhf));
        *(uint4*)(d_apack + (size_t)(mt * NCHUNK + kc) * TILE_U32 + fragq * 128 + lane * 4) = v;
    } else {
        // ---- B pack: 2 fragments per thread, coalesced uint2 stores ----
        int nt = y - 16;
        #pragma unroll
        for (int q = 0; q < 2; q++) {
            int fragq = (t >> 5) + q * 16;   // 0..31
            int ki = fragq >> 4, ni = fragq & 15;
            int gb = lane >> 2, tg = lane & 3;
            int i = nt * 128 + ni * 8 + gb;  // weight row = output column
            int k0 = kc * 32 + ki * 16 + tg * 2;
            int k1 = k0 + 8;
            const float* wrow = combw + (size_t)i * KIN;
            float a0 = (k0     < KIN) ? wrow[k0]     : 0.f;
            float a1 = (k0 + 1 < KIN) ? wrow[k0 + 1] : 0.f;
            float b0 = (k1     < KIN) ? wrow[k1]     : 0.f;
            float b1 = (k1 + 1 < KIN) ? wrow[k1 + 1] : 0.f;
            uint2 v;
            v.x = pack_bf16(a0, a1);
            v.y = pack_bf16(b0, b1);
            *(uint2*)(d_bpack + (size_t)(nt * NCHUNK + kc) * TILE_U32 + fragq * 64 + lane * 2) = v;
        }
    }
}

// ---------------- stage loader: 16KB, 128 threads ----------------
__device__ __forceinline__ void load_stage(uint32_t sbase, int s,
                                           const uint32_t* aP, const uint32_t* bP, int tid) {
    uint32_t dst = sbase + s * STAGE_B + tid * 16;
    #pragma unroll
    for (int j = 0; j < 4; j++) CP_ASYNC16(dst + j * 2048, aP + tid * 4 + j * 512);
    dst += 8192;
    #pragma unroll
    for (int j = 0; j < 4; j++) CP_ASYNC16(dst + j * 2048, bP + tid * 4 + j * 512);
}

// ---------------- bf16 mma GEMM: C[128x128] per CTA, 4 warps 64x64 each --------
__global__ __launch_bounds__(128, 2) void k_gemm_mma(const float* __restrict__ bias,
                                                     float* __restrict__ C) {
    extern __shared__ __align__(16) uint32_t smu[];
    int tid = threadIdx.x, lane = tid & 31, wid = tid >> 5;
    int warpM = wid & 1, warpN = wid >> 1;      // 2 x 2 warps, 64x64 each
    int mt = blockIdx.y, nt = blockIdx.x;
    const uint32_t* aP0 = d_apack + (size_t)mt * NCHUNK * TILE_U32;
    const uint32_t* bP0 = d_bpack + (size_t)nt * NCHUNK * TILE_U32;
    uint32_t sbase = smem_u32(smu);

    float acc[4][8][4];
    #pragma unroll
    for (int m = 0; m < 4; m++)
        #pragma unroll
        for (int n = 0; n < 8; n++)
            #pragma unroll
            for (int q = 0; q < 4; q++) acc[m][n][q] = 0.f;

    #pragma unroll
    for (int p = 0; p < NSTG - 1; p++) {
        load_stage(sbase, p, aP0 + (size_t)p * TILE_U32, bP0 + (size_t)p * TILE_U32, tid);
        CP_COMMIT();
    }

    for (int kc = 0; kc < NCHUNK; kc++) {
        CP_WAIT(NSTG - 2);
        __syncthreads();
        int pf = kc + NSTG - 1;
        if (pf < NCHUNK)
            load_stage(sbase, pf % NSTG, aP0 + (size_t)pf * TILE_U32,
                       bP0 + (size_t)pf * TILE_U32, tid);
        CP_COMMIT();

        const uint32_t* As = smu + (kc % NSTG) * STAGE_U32;
        const uint32_t* Bs = As + TILE_U32;
        #pragma unroll
        for (int ki = 0; ki < 2; ki++) {
            uint32_t af[4][4];
            #pragma unroll
            for (int m = 0; m < 4; m++) {
                uint4 v = *(const uint4*)(As + ((ki * 8 + warpM * 4 + m) * 128 + lane * 4));
                af[m][0] = v.x; af[m][1] = v.y; af[m][2] = v.z; af[m][3] = v.w;
            }
            uint32_t bf[8][2];
            #pragma unroll
            for (int n = 0; n < 8; n++) {
                uint2 w = *(const uint2*)(Bs + ((ki * 16 + warpN * 8 + n) * 64 + lane * 2));
                bf[n][0] = w.x; bf[n][1] = w.y;
            }
            #pragma unroll
            for (int m = 0; m < 4; m++)
                #pragma unroll
                for (int n = 0; n < 8; n++) MMA16(acc[m][n], af[m], bf[n]);
        }
    }

    // epilogue
    int g = lane >> 2, tg = lane & 3;
    int rowBase = mt * BM + warpM * 64;
    int colBase = nt * BN + warpN * 64;
    #pragma unroll
    for (int m = 0; m < 4; m++) {
        int r0 = rowBase + m * 16 + g;
        #pragma unroll
        for (int n = 0; n < 8; n++) {
            int c = colBase + n * 8 + tg * 2;
            float2 bb = *(const float2*)(bias + c);
            float2 o0 = { acc[m][n][0] + bb.x, acc[m][n][1] + bb.y };
            float2 o1 = { acc[m][n][2] + bb.x, acc[m][n][3] + bb.y };
            *(float2*)(C + (size_t)r0 * NN + c) = o0;
            *(float2*)(C + (size_t)(r0 + 8) * NN + c) = o1;
        }
    }
}

// ---------------- register-resident row log-softmax ----------------
__global__ void k_lsm(float* __restrict__ out) {
    int i = blockIdx.x;
    int t = threadIdx.x;                 // 256
    int lane = t & 31, wid = t >> 5;
    float4* rp = (float4*)(out + (size_t)i * NN);
    float4 v0 = rp[t];
    float4 v1 = rp[t + 256];

    float m = fmaxf(fmaxf(fmaxf(v0.x, v0.y), fmaxf(v0.z, v0.w)),
                    fmaxf(fmaxf(v1.x, v1.y), fmaxf(v1.z, v1.w)));
    #pragma unroll
    for (int o = 16; o; o >>= 1) m = fmaxf(m, __shfl_xor_sync(0xffffffffu, m, o));
    __shared__ float sA[8];
    __shared__ float sbc;
    if (lane == 0) sA[wid] = m;
    __syncthreads();
    if (t == 0) {
        float mm = sA[0];
        #pragma unroll
        for (int w = 1; w < 8; w++) mm = fmaxf(mm, sA[w]);
        sbc = mm;
    }
    __syncthreads();
    float mx = sbc;

    float s = __expf(v0.x - mx) + __expf(v0.y - mx) + __expf(v0.z - mx) + __expf(v0.w - mx)
            + __expf(v1.x - mx) + __expf(v1.y - mx) + __expf(v1.z - mx) + __expf(v1.w - mx);
    #pragma unroll
    for (int o = 16; o; o >>= 1) s += __shfl_xor_sync(0xffffffffu, s, o);
    __syncthreads();
    if (lane == 0) sA[wid] = s;
    __syncthreads();
    if (t == 0) {
        float ss = 0.f;
        #pragma unroll
        for (int w = 0; w < 8; w++) ss += sA[w];
        sbc = logf(ss) + mx;
    }
    __syncthreads();
    float lse = sbc;

    v0.x -= lse; v0.y -= lse; v0.z -= lse; v0.w -= lse;
    v1.x -= lse; v1.y -= lse; v1.z -= lse; v1.w -= lse;
    rp[t] = v0;
    rp[t + 256] = v1;
}

// ---------------- launch ----------------
extern "C" void kernel_launch(void* const* d_in, const int* in_sizes, int n_in,
                              void* d_out, int out_size) {
    const float* dist   = (const float*)d_in[0];
    const float* emb    = (const float*)d_in[1];
    const float* llw    = (const float*)d_in[2];
    const float* llb    = (const float*)d_in[3];
    const float* lrw    = (const float*)d_in[4];
    const float* ew     = (const float*)d_in[5];
    const float* edge_b = (const float*)d_in[6];
    const float* combw  = (const float*)d_in[7];
    const float* combb  = (const float*)d_in[8];
    const int*   stops  = (const int*)d_in[9];
    const int*   wk     = (const int*)d_in[10];
    const int*   vh     = (const int*)d_in[11];
    float* out = (float*)d_out;

    k_prep<<<1, NSTOP>>>(stops);
    k_initc<<<NN, DD>>>(emb);
    k_aggv3p<<<dim3(NSTOP / 2, 2), 256>>>();
    k_aggdiv<<<NSTOP, DD>>>();
    k_pref2<<<NN / 8, 256>>>(emb, llw, llb, lrw, ew);

    dim3 fg(NCHUNK, 32);
    k_fill<<<fg, 512>>>(dist, edge_b, wk, vh, combw);

    cudaFuncSetAttribute(k_gemm_mma, cudaFuncAttributeMaxDynamicSharedMemorySize, GEMM_SMEM);
    dim3 gg(NN / BN, NN / BM);
    k_gemm_mma<<<gg, 128, GEMM_SMEM>>>(combb, out);

    k_lsm<<<NN, 256>>>(out);
}

// round 17
// speedup vs baseline: 1.0153x; 1.0153x over previous
#include <cuda_runtime.h>
#include <cuda_bf16.h>
#include <math.h>
#include <stdint.h>

#define NN 2048
#define DD 64
#define PP 32
#define NSTOP 512
#define KIN 4131          // 2*N + 3 + P
#define KPAD 4160         // 130 chunks of 32
#define NCHUNK 130
#define BM 128
#define BN 128
#define NSTG 4
#define TILE_U32 2048     // 128x32 bf16 = 2048 uint32 = 8KB
#define STAGE_U32 4096
#define STAGE_B 16384
#define GEMM_SMEM (NSTG * STAGE_B)

// ---------------- scratch (device globals: allocation-free) ----------------
__device__ unsigned d_kmask[NN / 32];
__device__ int   d_kpre[NN / 32];    // exclusive prefix of popc(kmask)
__device__ int   d_klist[NSTOP];
__device__ int   d_nk;
__device__ __align__(16) float d_xn[NN * DD];
__device__ __align__(16) float d_xnc[NSTOP * DD];
__device__ __align__(16) float d_embc[NSTOP * DD];
__device__ __align__(16) float d_aggn[NN * DD];
__device__ float d_pref[NN * PP];
__device__ float d_av[NN];
__device__ float d_bv[NN];
// m16n8k16 bf16 fragment-packed operands
__device__ __align__(128) uint32_t d_apack[(size_t)NN * KPAD / 2];
__device__ __align__(128) uint32_t d_bpack[(size_t)NN * KPAD / 2];

// ---------------- helpers ----------------
__device__ __forceinline__ uint32_t smem_u32(const void* p) {
    uint32_t a;
    asm("{ .reg .u64 t; cvta.to.shared.u64 t, %1; cvt.u32.u64 %0, t; }" : "=r"(a) : "l"(p));
    return a;
}
__device__ __forceinline__ uint32_t pack_bf16(float a, float b) {
    __nv_bfloat162 h = __floats2bfloat162_rn(a, b);
    return *(uint32_t*)&h;
}
#define CP_ASYNC16(dst, src) \
    asm volatile("cp.async.cg.shared.global [%0], [%1], 16;" :: "r"(dst), "l"(src) : "memory")
#define CP_COMMIT() asm volatile("cp.async.commit_group;" ::: "memory")
#define CP_WAIT(n)  asm volatile("cp.async.wait_group %0;" :: "n"(n) : "memory")

#define MMA16(c, a, b) \
    asm volatile("mma.sync.aligned.m16n8k16.row.col.f32.bf16.bf16.f32 " \
        "{%0,%1,%2,%3},{%4,%5,%6,%7},{%8,%9},{%0,%1,%2,%3};" \
        : "+f"((c)[0]), "+f"((c)[1]), "+f"((c)[2]), "+f"((c)[3]) \
        : "r"((a)[0]), "r"((a)[1]), "r"((a)[2]), "r"((a)[3]), \
          "r"((b)[0]), "r"((b)[1]))

__device__ __forceinline__ int keep_bit(int i) {
    return (d_kmask[i >> 5] >> (i & 31)) & 1;
}

// ---------------- prep: zero mask, scatter stops, prefix table (1 block) ------
__global__ void k_prep(const int* __restrict__ stops) {      // 1 block, 512 thr
    __shared__ int cnt[NN / 32];
    int t = threadIdx.x;
    if (t < NN / 32) d_kmask[t] = 0u;
    __syncthreads();
    int s = stops[t];
    atomicOr(&d_kmask[s >> 5], 1u << (s & 31));
    __syncthreads();
    if (t < NN / 32) cnt[t] = __popc(d_kmask[t]);
    __syncthreads();
    if (t == 0) {
        int acc = 0;
        #pragma unroll
        for (int q = 0; q < NN / 32; q++) {
            d_kpre[q] = acc;
            acc += cnt[q];
        }
        d_nk = acc;
    }
}

// ---------------- fused: zero aggn + row-normalize + compaction ----------------
__global__ void k_initc(const float* __restrict__ emb) {     // grid NN, block 64
    int i = blockIdx.x;
    int t = threadIdx.x;
    int idx = i * DD + t;
    d_aggn[idx] = 0.f;

    float v = emb[idx];
    float s = v * v;
    #pragma unroll
    for (int o = 16; o; o >>= 1) s += __shfl_down_sync(0xffffffffu, s, o);
    __shared__ float ws[2];
    if ((t & 31) == 0) ws[t >> 5] = s;
    __syncthreads();
    float norm = fmaxf(sqrtf(ws[0] + ws[1]), 1e-8f);
    float xnv = v / norm;
    d_xn[idx] = xnv;

    unsigned w = d_kmask[i >> 5];
    if ((w >> (i & 31)) & 1) {
        int pos = d_kpre[i >> 5] + __popc(w & ((1u << (i & 31)) - 1u));
        if (t == 0) d_klist[pos] = i;
        d_xnc[pos * DD + t] = xnv;
        d_embc[pos * DD + t] = v;
    }
}

// ---------------- fused sim+agg: 2 kept-rows per block, 4 lanes per j ---------
__global__ void k_aggv3() {                                  // grid NSTOP/2, block 256
    int b0 = blockIdx.x * 2, t = threadIdx.x;
    int nk = d_nk;
    if (b0 >= nk) return;
    bool have1 = (b0 + 1) < nk;
    __shared__ __align__(16) float xi[2 * DD];
    __shared__ unsigned mw[2][16];
    __shared__ float agg0[256];
    __shared__ float agg1[256];
    if (t < 2 * DD) xi[t] = d_xnc[b0 * DD + t];   // two contiguous rows
    __syncthreads();

    int lane = t & 31, w = t >> 5;       // 8 warps; warp w owns j in [64w, 64w+64)
    int qt = lane & 3;                   // quarter of a row (16 floats)
    const float4* xq0 = (const float4*)(xi + qt * 16);
    const float4* xq1 = (const float4*)(xi + DD + qt * 16);
    float4 p0 = xq0[0], p1 = xq0[1], p2 = xq0[2], p3 = xq0[3];
    float4 q0 = xq1[0], q1 = xq1[1], q2 = xq1[2], q3 = xq1[3];

    unsigned w0 = 0, w1 = 0;
    #pragma unroll
    for (int sub = 0; sub < 8; sub++) {
        int j = w * 64 + sub * 8 + (lane >> 2);
        const float4* xj = (const float4*)(d_xnc + j * DD + qt * 16);
        float4 a0 = xj[0], a1 = xj[1], a2 = xj[2], a3 = xj[3];
        float s0 = a0.x * p0.x + a0.y * p0.y + a0.z * p0.z + a0.w * p0.w
                 + a1.x * p1.x + a1.y * p1.y + a1.z * p1.z + a1.w * p1.w
                 + a2.x * p2.x + a2.y * p2.y + a2.z * p2.z + a2.w * p2.w
                 + a3.x * p3.x + a3.y * p3.y + a3.z * p3.z + a3.w * p3.w;
        float s1 = a0.x * q0.x + a0.y * q0.y + a0.z * q0.z + a0.w * q0.w
                 + a1.x * q1.x + a1.y * q1.y + a1.z * q1.z + a1.w * q1.w
                 + a2.x * q2.x + a2.y * q2.y + a2.z * q2.z + a2.w * q2.w
                 + a3.x * q3.x + a3.y * q3.y + a3.z * q3.z + a3.w * q3.w;
        s0 += __shfl_xor_sync(0xffffffffu, s0, 1);
        s0 += __shfl_xor_sync(0xffffffffu, s0, 2);
        s1 += __shfl_xor_sync(0xffffffffu, s1, 1);
        s1 += __shfl_xor_sync(0xffffffffu, s1, 2);
        bool pr0 = (qt == 0) && (j < nk) && (j != b0) && (s0 > 0.5f);
        bool pr1 = (qt == 0) && have1 && (j < nk) && (j != b0 + 1) && (s1 > 0.5f);
        unsigned m0 = __ballot_sync(0xffffffffu, pr0);       // bits at 4r
        unsigned m1 = __ballot_sync(0xffffffffu, pr1);
        unsigned c0 = 0, c1 = 0;
        #pragma unroll
        for (int r = 0; r < 8; r++) {
            c0 |= ((m0 >> (4 * r)) & 1u) << r;
            c1 |= ((m1 >> (4 * r)) & 1u) << r;
        }
        w0 |= c0 << ((sub & 3) * 8);
        w1 |= c1 << ((sub & 3) * 8);
        if ((sub & 3) == 3) {
            if (lane == 0) {
                mw[0][w * 2 + (sub >> 2)] = w0;
                mw[1][w * 2 + (sub >> 2)] = w1;
            }
            w0 = 0; w1 = 0;
        }
    }
    __syncthreads();

    int deg0 = 0, deg1 = 0;
    #pragma unroll
    for (int q = 0; q < 16; q++) { deg0 += __popc(mw[0][q]); deg1 += __popc(mw[1][q]); }

    int d = t & 63, part = t >> 6;       // 4 parts x 4 words each
    float s0 = 0.f, s1 = 0.f;
    #pragma unroll
    for (int q = part * 4; q < part * 4 + 4; q++) {
        unsigned mm = mw[0][q];
        while (mm) {
            int bit = __ffs(mm) - 1;
            mm &= mm - 1;
            s0 += d_embc[(q * 32 + bit) * DD + d];
        }
        mm = mw[1][q];
        while (mm) {
            int bit = __ffs(mm) - 1;
            mm &= mm - 1;
            s1 += d_embc[(q * 32 + bit) * DD + d];
        }
    }
    agg0[t] = s0;
    agg1[t] = s1;
    __syncthreads();
    if (t < DD) {
        float s = agg0[t] + agg0[t + 64] + agg0[t + 128] + agg0[t + 192];
        d_aggn[d_klist[b0] * DD + t] = s / fmaxf((float)deg0, 1.0f);
    } else if (t < 2 * DD && have1) {
        int dd = t - DD;
        float s = agg1[dd] + agg1[dd + 64] + agg1[dd + 128] + agg1[dd + 192];
        d_aggn[d_klist[b0 + 1] * DD + dd] = s / fmaxf((float)deg1, 1.0f);
    }
}

// ---------------- pref v2: smem-staged weights, 8 rows/block ----------------
__global__ __launch_bounds__(256) void k_pref2(const float* __restrict__ emb,
                       const float* __restrict__ llw, const float* __restrict__ llb,
                       const float* __restrict__ lrw, const float* __restrict__ ew) {
    __shared__ float wl[DD * PP];        // transposed: wl[d*32+p]
    __shared__ float wr[DD * PP];
    __shared__ float rows[8 * 2 * DD];   // per row: agg[64] then emb[64]
    int t = threadIdx.x;
    int i0 = blockIdx.x * 8;
    #pragma unroll
    for (int q = 0; q < 8; q++) {
        int idx = q * 256 + t;           // idx = p*64+d
        int p = idx >> 6, d = idx & 63;
        wl[d * PP + p] = llw[idx];
        wr[d * PP + p] = lrw[idx];
    }
    #pragma unroll
    for (int q = 0; q < 2; q++) {
        int idx = q * 256 + t;           // 512 floats each array
        int r = idx >> 6, d = idx & 63;
        rows[r * 128 + d] = d_aggn[(i0 + r) * DD + d];
        rows[r * 128 + 64 + d] = emb[(i0 + r) * DD + d];
    }
    __syncthreads();

    int r = t >> 5, p = t & 31;
    int i = i0 + r;
    const float* ar = rows + r * 128;
    const float* er = ar + DD;
    float s = llb[p];
    #pragma unroll
    for (int d = 0; d < DD; d++)
        s += ar[d] * wl[d * PP + p] + er[d] * wr[d * PP + p];
    d_pref[i * PP + p] = s;
    float a = s * ew[p];
    float b = s * ew[PP + p];
    #pragma unroll
    for (int o = 16; o; o >>= 1) {
        a += __shfl_down_sync(0xffffffffu, a, o);
        b += __shfl_down_sync(0xffffffffu, b, o);
    }
    if (p == 0) { d_av[i] = a; d_bv[i] = b; }
}

// ---------------- combined value at (i,k) ----------------
__device__ __forceinline__ float comb_val(int i, int k, const float* __restrict__ dist,
                                          float eb, float wkf, float vhf) {
    if (k < PP) return d_pref[i * PP + k];
    if (k < PP + NN) {
        float e = d_av[i] + d_bv[k - PP] + eb;
        return (e >= 0.f) ? e : 0.01f * e;
    }
    if (k < PP + 2 * NN) return dist[(size_t)i * NN + (k - PP - NN)];
    if (k == PP + 2 * NN) return wkf;
    if (k == PP + 2 * NN + 1) return vhf;
    if (k == PP + 2 * NN + 2) return keep_bit(i) ? 1.f : 0.f;
    return 0.f;
}

// ---------------- merged fill: y<16 -> A pack, y>=16 -> B pack ----------------
__global__ __launch_bounds__(512) void k_fill(const float* __restrict__ dist,
                                              const float* __restrict__ edge_b,
                                              const int* __restrict__ wk,
                                              const int* __restrict__ vh,
                                              const float* __restrict__ combw) {
    int kc = blockIdx.x;
    int y = blockIdx.y;
    int t = threadIdx.x;                 // 512
    int lane = t & 31;
    if (y < 16) {
        // ---- A pack: fragment-offset iteration, coalesced uint4 stores ----
        int mt = y;
        int fragq = t >> 5;              // 0..15
        int ki = fragq >> 3, mi = fragq & 7;
        int g = lane >> 2, tg = lane & 3;
        int i0 = mt * 128 + mi * 16 + g;
        int i1 = i0 + 8;
        int kA = kc * 32 + ki * 16 + tg * 2;
        int kB = kA + 8;
        float eb = edge_b[0], wkf = (float)wk[0], vhf = (float)vh[0];
        uint4 v;
        v.x = pack_bf16(comb_val(i0, kA, dist, eb, wkf, vhf), comb_val(i0, kA + 1, dist, eb, wkf, vhf));
        v.y = pack_bf16(comb_val(i1, kA, dist, eb, wkf, vhf), comb_val(i1, kA + 1, dist, eb, wkf, vhf));
        v.z = pack_bf16(comb_val(i0, kB, dist, eb, wkf, vhf), comb_val(i0, kB + 1, dist, eb, wkf, vhf));
        v.w = pack_bf16(comb_val(i1, kB, dist, eb, wkf, vhf), comb_val(i1, kB + 1, dist, eb, wkf, vhf));
        *(uint4*)(d_apack + (size_t)(mt * NCHUNK + kc) * TILE_U32 + fragq * 128 + lane * 4) = v;
    } else {
        // ---- B pack: 2 fragments per thread, coalesced uint2 stores ----
        int nt = y - 16;
        #pragma unroll
        for (int q = 0; q < 2; q++) {
            int fragq = (t >> 5) + q * 16;   // 0..31
            int ki = fragq >> 4, ni = fragq & 15;
            int gb = lane >> 2, tg = lane & 3;
            int i = nt * 128 + ni * 8 + gb;  // weight row = output column
            int k0 = kc * 32 + ki * 16 + tg * 2;
            int k1 = k0 + 8;
            const float* wrow = combw + (size_t)i * KIN;
            float a0 = (k0     < KIN) ? wrow[k0]     : 0.f;
            float a1 = (k0 + 1 < KIN) ? wrow[k0 + 1] : 0.f;
            float b0 = (k1     < KIN) ? wrow[k1]     : 0.f;
            float b1 = (k1 + 1 < KIN) ? wrow[k1 + 1] : 0.f;
            uint2 v;
            v.x = pack_bf16(a0, a1);
            v.y = pack_bf16(b0, b1);
            *(uint2*)(d_bpack + (size_t)(nt * NCHUNK + kc) * TILE_U32 + fragq * 64 + lane * 2) = v;
        }
    }
}

// ---------------- stage loader: 16KB, 128 threads ----------------
__device__ __forceinline__ void load_stage(uint32_t sbase, int s,
                                           const uint32_t* aP, const uint32_t* bP, int tid) {
    uint32_t dst = sbase + s * STAGE_B + tid * 16;
    #pragma unroll
    for (int j = 0; j < 4; j++) CP_ASYNC16(dst + j * 2048, aP + tid * 4 + j * 512);
    dst += 8192;
    #pragma unroll
    for (int j = 0; j < 4; j++) CP_ASYNC16(dst + j * 2048, bP + tid * 4 + j * 512);
}

// ---------------- bf16 mma GEMM: C[128x128] per CTA, 4 warps 64x64 each --------
__global__ __launch_bounds__(128, 2) void k_gemm_mma(const float* __restrict__ bias,
                                                     float* __restrict__ C) {
    extern __shared__ __align__(16) uint32_t smu[];
    int tid = threadIdx.x, lane = tid & 31, wid = tid >> 5;
    int warpM = wid & 1, warpN = wid >> 1;      // 2 x 2 warps, 64x64 each
    int mt = blockIdx.y, nt = blockIdx.x;
    const uint32_t* aP0 = d_apack + (size_t)mt * NCHUNK * TILE_U32;
    const uint32_t* bP0 = d_bpack + (size_t)nt * NCHUNK * TILE_U32;
    uint32_t sbase = smem_u32(smu);

    float acc[4][8][4];
    #pragma unroll
    for (int m = 0; m < 4; m++)
        #pragma unroll
        for (int n = 0; n < 8; n++)
            #pragma unroll
            for (int q = 0; q < 4; q++) acc[m][n][q] = 0.f;

    #pragma unroll
    for (int p = 0; p < NSTG - 1; p++) {
        load_stage(sbase, p, aP0 + (size_t)p * TILE_U32, bP0 + (size_t)p * TILE_U32, tid);
        CP_COMMIT();
    }

    for (int kc = 0; kc < NCHUNK; kc++) {
        CP_WAIT(NSTG - 2);
        __syncthreads();
        int pf = kc + NSTG - 1;
        if (pf < NCHUNK)
            load_stage(sbase, pf % NSTG, aP0 + (size_t)pf * TILE_U32,
                       bP0 + (size_t)pf * TILE_U32, tid);
        CP_COMMIT();

        const uint32_t* As = smu + (kc % NSTG) * STAGE_U32;
        const uint32_t* Bs = As + TILE_U32;
        #pragma unroll
        for (int ki = 0; ki < 2; ki++) {
            uint32_t af[4][4];
            #pragma unroll
            for (int m = 0; m < 4; m++) {
                uint4 v = *(const uint4*)(As + ((ki * 8 + warpM * 4 + m) * 128 + lane * 4));
                af[m][0] = v.x; af[m][1] = v.y; af[m][2] = v.z; af[m][3] = v.w;
            }
            uint32_t bf[8][2];
            #pragma unroll
            for (int n = 0; n < 8; n++) {
                uint2 w = *(const uint2*)(Bs + ((ki * 16 + warpN * 8 + n) * 64 + lane * 2));
                bf[n][0] = w.x; bf[n][1] = w.y;
            }
            #pragma unroll
            for (int m = 0; m < 4; m++)
                #pragma unroll
                for (int n = 0; n < 8; n++) MMA16(acc[m][n], af[m], bf[n]);
        }
    }

    // epilogue
    int g = lane >> 2, tg = lane & 3;
    int rowBase = mt * BM + warpM * 64;
    int colBase = nt * BN + warpN * 64;
    #pragma unroll
    for (int m = 0; m < 4; m++) {
        int r0 = rowBase + m * 16 + g;
        #pragma unroll
        for (int n = 0; n < 8; n++) {
            int c = colBase + n * 8 + tg * 2;
            float2 bb = *(const float2*)(bias + c);
            float2 o0 = { acc[m][n][0] + bb.x, acc[m][n][1] + bb.y };
            float2 o1 = { acc[m][n][2] + bb.x, acc[m][n][3] + bb.y };
            *(float2*)(C + (size_t)r0 * NN + c) = o0;
            *(float2*)(C + (size_t)(r0 + 8) * NN + c) = o1;
        }
    }
}

// ---------------- register-resident row log-softmax ----------------
__global__ void k_lsm(float* __restrict__ out) {
    int i = blockIdx.x;
    int t = threadIdx.x;                 // 256
    int lane = t & 31, wid = t >> 5;
    float4* rp = (float4*)(out + (size_t)i * NN);
    float4 v0 = rp[t];
    float4 v1 = rp[t + 256];

    float m = fmaxf(fmaxf(fmaxf(v0.x, v0.y), fmaxf(v0.z, v0.w)),
                    fmaxf(fmaxf(v1.x, v1.y), fmaxf(v1.z, v1.w)));
    #pragma unroll
    for (int o = 16; o; o >>= 1) m = fmaxf(m, __shfl_xor_sync(0xffffffffu, m, o));
    __shared__ float sA[8];
    __shared__ float sbc;
    if (lane == 0) sA[wid] = m;
    __syncthreads();
    if (t == 0) {
        float mm = sA[0];
        #pragma unroll
        for (int w = 1; w < 8; w++) mm = fmaxf(mm, sA[w]);
        sbc = mm;
    }
    __syncthreads();
    float mx = sbc;

    float s = __expf(v0.x - mx) + __expf(v0.y - mx) + __expf(v0.z - mx) + __expf(v0.w - mx)
            + __expf(v1.x - mx) + __expf(v1.y - mx) + __expf(v1.z - mx) + __expf(v1.w - mx);
    #pragma unroll
    for (int o = 16; o; o >>= 1) s += __shfl_xor_sync(0xffffffffu, s, o);
    __syncthreads();
    if (lane == 0) sA[wid] = s;
    __syncthreads();
    if (t == 0) {
        float ss = 0.f;
        #pragma unroll
        for (int w = 0; w < 8; w++) ss += sA[w];
        sbc = logf(ss) + mx;
    }
    __syncthreads();
    float lse = sbc;

    v0.x -= lse; v0.y -= lse; v0.z -= lse; v0.w -= lse;
    v1.x -= lse; v1.y -= lse; v1.z -= lse; v1.w -= lse;
    rp[t] = v0;
    rp[t + 256] = v1;
}

// ---------------- launch ----------------
extern "C" void kernel_launch(void* const* d_in, const int* in_sizes, int n_in,
                              void* d_out, int out_size) {
    const float* dist   = (const float*)d_in[0];
    const float* emb    = (const float*)d_in[1];
    const float* llw    = (const float*)d_in[2];
    const float* llb    = (const float*)d_in[3];
    const float* lrw    = (const float*)d_in[4];
    const float* ew     = (const float*)d_in[5];
    const float* edge_b = (const float*)d_in[6];
    const float* combw  = (const float*)d_in[7];
    const float* combb  = (const float*)d_in[8];
    const int*   stops  = (const int*)d_in[9];
    const int*   wk     = (const int*)d_in[10];
    const int*   vh     = (const int*)d_in[11];
    float* out = (float*)d_out;

    k_prep<<<1, NSTOP>>>(stops);
    k_initc<<<NN, DD>>>(emb);
    k_aggv3<<<NSTOP / 2, 256>>>();
    k_pref2<<<NN / 8, 256>>>(emb, llw, llb, lrw, ew);

    dim3 fg(NCHUNK, 32);
    k_fill<<<fg, 512>>>(dist, edge_b, wk, vh, combw);

    cudaFuncSetAttribute(k_gemm_mma, cudaFuncAttributeMaxDynamicSharedMemorySize, GEMM_SMEM);
    dim3 gg(NN / BN, NN / BM);
    k_gemm_mma<<<gg, 128, GEMM_SMEM>>>(combb, out);

    k_lsm<<<NN, 256>>>(out);
}